// round 3
// baseline (speedup 1.0000x reference)
#include <cuda_runtime.h>
#include <cuda_bf16.h>

#define N_UNITS  8
#define M_ATOMS  1024
#define NPTS     (N_UNITS * M_ATOMS)

#define IPT      4                 // i-points per thread (256 thr * 4 = 1024 rows)
#define JCH      64                // j-points per block chunk
#define NJC      (M_ATOMS / JCH)   // 16 j-chunks per unit pair
#define NPAIRS   28                // 8 choose 2

// Pre-scaled points: (sx, sy, sz, b) with s = sqrt(2*log2(e)) * p,
// b = log2(e) * (0.5 - |p|^2). Then log2(pen_ij) = b_i + b_j + s_i . s_j,
// and the row-sum factors as 2^{b_i} * sum_j 2^{b_j + s_i.s_j} — moving one
// exp per pair out of the pair loop entirely.
__device__ float4 g_pts[NPTS];

__device__ __forceinline__ float ex2f(float x) {
    float y;
    asm("ex2.approx.f32 %0, %1;" : "=f"(y) : "f"(x));
    return y;
}

// ---------------------------------------------------------------------------
// Kernel 1: rotate + translate points, emit pre-scaled (s, b); reduce L1;
// thread 0 of block 0 adds L_com. 32 blocks x 256 threads = 8192 points.
// ---------------------------------------------------------------------------
__global__ void __launch_bounds__(256)
transform_kernel(const float* __restrict__ positions,
                 const float* __restrict__ euler,
                 const float* __restrict__ coords,
                 float* __restrict__ out)
{
    const float LOG2E = 1.4426950408889634f;
    const float CSC   = 1.69864122f;   // sqrt(2*LOG2E)

    int p = blockIdx.x * 256 + threadIdx.x;   // global point index
    int n = p >> 10;                          // unit
    int m = p & (M_ATOMS - 1);                // atom

    float phi   = euler[n * 3 + 0];
    float theta = euler[n * 3 + 1];
    float psi   = euler[n * 3 + 2];
    float sp, cp, st, ct, ss, cs;
    sincosf(phi,   &sp, &cp);
    sincosf(theta, &st, &ct);
    sincosf(psi,   &ss, &cs);

    // R = Rz(psi) * Ry(theta) * Rx(phi)
    float r00 = cs * ct;
    float r01 = cs * st * sp - ss * cp;
    float r02 = cs * st * cp + ss * sp;
    float r10 = ss * ct;
    float r11 = ss * st * sp + cs * cp;
    float r12 = ss * st * cp - cs * sp;
    float r20 = -st;
    float r21 = ct * sp;
    float r22 = ct * cp;

    float cx = coords[m * 3 + 0];
    float cy = coords[m * 3 + 1];
    float cz = coords[m * 3 + 2];

    float tx = fmaf(r00, cx, fmaf(r01, cy, fmaf(r02, cz, positions[n * 3 + 0])));
    float ty = fmaf(r10, cx, fmaf(r11, cy, fmaf(r12, cz, positions[n * 3 + 1])));
    float tz = fmaf(r20, cx, fmaf(r21, cy, fmaf(r22, cz, positions[n * 3 + 2])));

    float sq = fmaf(tx, tx, fmaf(ty, ty, tz * tz));

    float4 q;
    q.x = CSC * tx;
    q.y = CSC * ty;
    q.z = CSC * tz;
    q.w = fmaf(-LOG2E, sq, 0.5f * LOG2E);
    g_pts[p] = q;

    // ---- reduce sum of squares for L1 = total / N_UNITS ----
    float v = sq;
    #pragma unroll
    for (int off = 16; off > 0; off >>= 1)
        v += __shfl_down_sync(0xffffffffu, v, off);

    __shared__ float wsum[8];
    int lane = threadIdx.x & 31;
    int wid  = threadIdx.x >> 5;
    if (lane == 0) wsum[wid] = v;
    __syncthreads();
    if (threadIdx.x == 0) {
        float t = 0.f;
        #pragma unroll
        for (int w = 0; w < 8; ++w) t += wsum[w];
        atomicAdd(out, t * (1.0f / N_UNITS));
    }

    // ---- L_com (once, ALPHA = 1) ----
    if (p == 0) {
        float sx = 0.f, sy = 0.f, sz = 0.f;
        #pragma unroll
        for (int u = 0; u < N_UNITS; ++u) {
            sx += positions[u * 3 + 0];
            sy += positions[u * 3 + 1];
            sz += positions[u * 3 + 2];
        }
        atomicAdd(out, fmaf(sx, sx, fmaf(sy, sy, sz * sz)));
    }
}

// ---------------------------------------------------------------------------
// Kernel 2: masked pairwise interaction.
// Block = (unit pair (u<v), j-chunk). 256 threads x IPT=4 i-rows of unit u;
// JCH=64 j-points of unit v staged in shared. Inner loop per pair:
// 3 FFMA (dot seeded with b_j) + 1 ex2 + 1 FADD — FMA pipe (8 cyc / 32
// pairs / SMSP) and MUFU pipe (8 cyc) exactly balanced. 448 blocks =
// 24 warps/SM: whole grid fits in one wave.
// ---------------------------------------------------------------------------
__global__ void __launch_bounds__(256)
pair_kernel(float* __restrict__ out)
{
    __shared__ float4 shj[JCH];
    __shared__ float  wpart[8];

    int b       = blockIdx.x;
    int pairIdx = b / NJC;
    int jc      = b - pairIdx * NJC;

    // triangular index -> (u, v), u < v
    int u = 0, rem = pairIdx;
    while (rem >= (N_UNITS - 1 - u)) { rem -= (N_UNITS - 1 - u); ++u; }
    int v = u + 1 + rem;

    int tid = threadIdx.x;
    if (tid < JCH)
        shj[tid] = g_pts[v * M_ATOMS + jc * JCH + tid];

    float sx[IPT], sy[IPT], sz[IPT], fi[IPT], acc[IPT];
    #pragma unroll
    for (int k = 0; k < IPT; ++k) {
        float4 q = g_pts[u * M_ATOMS + tid + k * 256];
        sx[k] = q.x; sy[k] = q.y; sz[k] = q.z;
        fi[k] = ex2f(q.w);            // row factor 2^{b_i}, hoisted
        acc[k] = 0.f;
    }
    __syncthreads();

    #pragma unroll 4
    for (int jj = 0; jj < JCH; ++jj) {
        float4 pj = shj[jj];          // broadcast LDS.128, conflict-free
        #pragma unroll
        for (int k = 0; k < IPT; ++k) {
            float t = fmaf(sx[k], pj.x, pj.w);
            t = fmaf(sy[k], pj.y, t);
            t = fmaf(sz[k], pj.z, t);
            acc[k] += ex2f(t);
        }
    }

    float s = 0.f;
    #pragma unroll
    for (int k = 0; k < IPT; ++k)
        s = fmaf(acc[k], fi[k], s);

    #pragma unroll
    for (int off = 16; off > 0; off >>= 1)
        s += __shfl_down_sync(0xffffffffu, s, off);

    int lane = tid & 31;
    int wid  = tid >> 5;
    if (lane == 0) wpart[wid] = s;
    __syncthreads();
    if (tid == 0) {
        float t = 0.f;
        #pragma unroll
        for (int w = 0; w < 8; ++w) t += wpart[w];
        atomicAdd(out, 0.5f * t);     // LAMBDA1 = 0.5
    }
}

// ---------------------------------------------------------------------------
extern "C" void kernel_launch(void* const* d_in, const int* in_sizes, int n_in,
                              void* d_out, int out_size)
{
    const float* positions = (const float*)d_in[0];
    const float* euler     = (const float*)d_in[1];
    const float* coords    = (const float*)d_in[2];
    float*       out       = (float*)d_out;

    cudaMemsetAsync(out, 0, sizeof(float));
    transform_kernel<<<NPTS / 256, 256>>>(positions, euler, coords, out);
    pair_kernel<<<NPAIRS * NJC, 256>>>(out);
}

// round 5
// speedup vs baseline: 1.0119x; 1.0119x over previous
#include <cuda_runtime.h>
#include <cuda_bf16.h>

#define N_UNITS  8
#define M_ATOMS  1024
#define NPTS     (N_UNITS * M_ATOMS)

#define IPT      4                 // i-points per thread (256 thr * 4 = 1024 rows)
#define JCH      64                // j-points per block chunk
#define NJC      (M_ATOMS / JCH)   // 16 j-chunks per unit pair
#define NPAIRS   28                // 8 choose 2

// Pre-scaled points: (sx, sy, sz, b) with s = sqrt(2*log2(e)) * p,
// b = log2(e) * (0.5 - |p|^2). Then log2(pen_ij) = b_i + b_j + s_i . s_j,
// row-sum factors as 2^{b_i} * sum_j 2^{b_j + s_i.s_j}.
__device__ float4 g_pts[NPTS];

__device__ __forceinline__ float ex2f(float x) {
    float y;
    asm("ex2.approx.f32 %0, %1;" : "=f"(y) : "f"(x));
    return y;
}

// ---- packed f32x2 helpers (sm_100+; FFMA2 only reachable via PTX) ----
__device__ __forceinline__ unsigned long long pack2(float a, float b) {
    unsigned long long d;
    asm("mov.b64 %0, {%1, %2};" : "=l"(d) : "f"(a), "f"(b));
    return d;
}
__device__ __forceinline__ unsigned long long fma2(unsigned long long a,
                                                   unsigned long long b,
                                                   unsigned long long c) {
    unsigned long long d;
    asm("fma.rn.f32x2 %0, %1, %2, %3;" : "=l"(d) : "l"(a), "l"(b), "l"(c));
    return d;
}
__device__ __forceinline__ void unpack2(unsigned long long d, float& a, float& b) {
    asm("mov.b64 {%0, %1}, %2;" : "=f"(a), "=f"(b) : "l"(d));
}

// ---------------------------------------------------------------------------
// Kernel 1: rotate + translate points, emit pre-scaled (s, b); reduce L1;
// thread 0 of block 0 adds L_com. 32 blocks x 256 threads = 8192 points.
// ---------------------------------------------------------------------------
__global__ void __launch_bounds__(256)
transform_kernel(const float* __restrict__ positions,
                 const float* __restrict__ euler,
                 const float* __restrict__ coords,
                 float* __restrict__ out)
{
    const float LOG2E = 1.4426950408889634f;
    const float CSC   = 1.69864122f;   // sqrt(2*LOG2E)

    int p = blockIdx.x * 256 + threadIdx.x;   // global point index
    int n = p >> 10;                          // unit
    int m = p & (M_ATOMS - 1);                // atom

    float phi   = euler[n * 3 + 0];
    float theta = euler[n * 3 + 1];
    float psi   = euler[n * 3 + 2];
    float sp, cp, st, ct, ss, cs;
    __sincosf(phi,   &sp, &cp);   // fast MUFU path; |angle| <~ 4, error << 1e-3 budget
    __sincosf(theta, &st, &ct);
    __sincosf(psi,   &ss, &cs);

    // R = Rz(psi) * Ry(theta) * Rx(phi)
    float r00 = cs * ct;
    float r01 = cs * st * sp - ss * cp;
    float r02 = cs * st * cp + ss * sp;
    float r10 = ss * ct;
    float r11 = ss * st * sp + cs * cp;
    float r12 = ss * st * cp - cs * sp;
    float r20 = -st;
    float r21 = ct * sp;
    float r22 = ct * cp;

    float cx = coords[m * 3 + 0];
    float cy = coords[m * 3 + 1];
    float cz = coords[m * 3 + 2];

    float tx = fmaf(r00, cx, fmaf(r01, cy, fmaf(r02, cz, positions[n * 3 + 0])));
    float ty = fmaf(r10, cx, fmaf(r11, cy, fmaf(r12, cz, positions[n * 3 + 1])));
    float tz = fmaf(r20, cx, fmaf(r21, cy, fmaf(r22, cz, positions[n * 3 + 2])));

    float sq = fmaf(tx, tx, fmaf(ty, ty, tz * tz));

    float4 q;
    q.x = CSC * tx;
    q.y = CSC * ty;
    q.z = CSC * tz;
    q.w = fmaf(-LOG2E, sq, 0.5f * LOG2E);
    g_pts[p] = q;

    // ---- reduce sum of squares for L1 = total / N_UNITS ----
    float v = sq;
    #pragma unroll
    for (int off = 16; off > 0; off >>= 1)
        v += __shfl_down_sync(0xffffffffu, v, off);

    __shared__ float wsum[8];
    int lane = threadIdx.x & 31;
    int wid  = threadIdx.x >> 5;
    if (lane == 0) wsum[wid] = v;
    __syncthreads();
    if (threadIdx.x == 0) {
        float t = 0.f;
        #pragma unroll
        for (int w = 0; w < 8; ++w) t += wsum[w];
        atomicAdd(out, t * (1.0f / N_UNITS));
    }

    // ---- L_com (once, ALPHA = 1) ----
    if (p == 0) {
        float sx = 0.f, sy = 0.f, sz = 0.f;
        #pragma unroll
        for (int u = 0; u < N_UNITS; ++u) {
            sx += positions[u * 3 + 0];
            sy += positions[u * 3 + 1];
            sz += positions[u * 3 + 2];
        }
        atomicAdd(out, fmaf(sx, sx, fmaf(sy, sy, sz * sz)));
    }
}

// ---------------------------------------------------------------------------
// Kernel 2: masked pairwise interaction, f32x2-packed.
// Block = (unit pair (u<v), j-chunk). 256 threads x IPT=4 i-rows of unit u
// packed as 2 f32x2 lanes; JCH=64 j-points of unit v staged in shared with
// components pre-DUPLICATED: shA[j]=((x,x),(y,y)), shB[j]=((z,z),(w,w)) so
// broadcast LDS.128 yields ready-to-use f32x2 operands (no packing MOVs).
// Per warp per jj (128 pairs): fma pipe 10 insts (20 cyc), MUFU 4 insts
// (32 cyc) -> MUFU-bound at 8 cyc / 32 pairs, the irreducible floor.
// ---------------------------------------------------------------------------
__global__ void __launch_bounds__(256)
pair_kernel(float* __restrict__ out)
{
    __shared__ ulonglong2 shA[JCH];   // ((x,x),(y,y)) per j
    __shared__ ulonglong2 shB[JCH];   // ((z,z),(w,w)) per j
    __shared__ float wpart[8];

    int b       = blockIdx.x;
    int pairIdx = b / NJC;
    int jc      = b - pairIdx * NJC;

    // triangular index -> (u, v), u < v
    int u = 0, rem = pairIdx;
    while (rem >= (N_UNITS - 1 - u)) { rem -= (N_UNITS - 1 - u); ++u; }
    int v = u + 1 + rem;

    int tid = threadIdx.x;
    if (tid < JCH) {
        float4 q = g_pts[v * M_ATOMS + jc * JCH + tid];
        ulonglong2 A, B;
        A.x = pack2(q.x, q.x);
        A.y = pack2(q.y, q.y);
        B.x = pack2(q.z, q.z);
        B.y = pack2(q.w, q.w);
        shA[tid] = A;
        shB[tid] = B;
    }

    // i-rows: k = 0..3 -> indices tid + 256k; packed as (k0,k1) and (k2,k3)
    unsigned long long sx2[2], sy2[2], sz2[2];
    float fi[IPT], acc[IPT];
    {
        int base = u * M_ATOMS + tid;
        float4 q0 = g_pts[base + 0 * 256];
        float4 q1 = g_pts[base + 1 * 256];
        float4 q2 = g_pts[base + 2 * 256];
        float4 q3 = g_pts[base + 3 * 256];
        sx2[0] = pack2(q0.x, q1.x);  sx2[1] = pack2(q2.x, q3.x);
        sy2[0] = pack2(q0.y, q1.y);  sy2[1] = pack2(q2.y, q3.y);
        sz2[0] = pack2(q0.z, q1.z);  sz2[1] = pack2(q2.z, q3.z);
        fi[0] = ex2f(q0.w);  fi[1] = ex2f(q1.w);   // row factors 2^{b_i}
        fi[2] = ex2f(q2.w);  fi[3] = ex2f(q3.w);
        acc[0] = acc[1] = acc[2] = acc[3] = 0.f;
    }
    __syncthreads();

    #pragma unroll 8
    for (int jj = 0; jj < JCH; ++jj) {
        ulonglong2 A = shA[jj];       // broadcast LDS.128
        ulonglong2 B = shB[jj];       // broadcast LDS.128
        #pragma unroll
        for (int kp = 0; kp < 2; ++kp) {
            unsigned long long t = fma2(sx2[kp], A.x, B.y);  // seed with (w_j,w_j)
            t = fma2(sy2[kp], A.y, t);
            t = fma2(sz2[kp], B.x, t);
            float tlo, thi;
            unpack2(t, tlo, thi);     // register-pair alias when allocation cooperates
            acc[2 * kp + 0] += ex2f(tlo);
            acc[2 * kp + 1] += ex2f(thi);
        }
    }

    float s = 0.f;
    #pragma unroll
    for (int k = 0; k < IPT; ++k)
        s = fmaf(acc[k], fi[k], s);

    #pragma unroll
    for (int off = 16; off > 0; off >>= 1)
        s += __shfl_down_sync(0xffffffffu, s, off);

    int lane = tid & 31;
    int wid  = tid >> 5;
    if (lane == 0) wpart[wid] = s;
    __syncthreads();
    if (tid == 0) {
        float t = 0.f;
        #pragma unroll
        for (int w = 0; w < 8; ++w) t += wpart[w];
        atomicAdd(out, 0.5f * t);     // LAMBDA1 = 0.5
    }
}

// ---------------------------------------------------------------------------
extern "C" void kernel_launch(void* const* d_in, const int* in_sizes, int n_in,
                              void* d_out, int out_size)
{
    const float* positions = (const float*)d_in[0];
    const float* euler     = (const float*)d_in[1];
    const float* coords    = (const float*)d_in[2];
    float*       out       = (float*)d_out;

    cudaMemsetAsync(out, 0, sizeof(float));
    transform_kernel<<<NPTS / 256, 256>>>(positions, euler, coords, out);
    pair_kernel<<<NPAIRS * NJC, 256>>>(out);
}